// round 1
// baseline (speedup 1.0000x reference)
#include <cuda_runtime.h>
#include <math.h>

// SupConLoss fused kernel for GB300 (sm_103a).
// Losses:
//   ce     = -mean(log_softmax(predicts)[i, tgt[i]])
//   cl     = supervised contrastive over G = feats@feats^T / 0.1 (mask: same label, no diag)
//   triple = class-collapsed nt_xent_loss2 over G / 0.05
// out = 0.5*ce + 0.5*cl + 0.25*triple   (ALPHA = 0.5)

#define KD      128     // feature dim (fixed)
#define TM      16      // rows per block in main pass
#define TN      128     // j-tile
#define SJP     132     // padded row stride in shared (conflict-free LDS.128)
#define CLS_MAX 64
#define NMAX    4096

__device__ __align__(16) float g_feats[NMAX * KD];
__device__ int   g_cnt[CLS_MAX];
__device__ float g_rowCe[NMAX];
__device__ float g_rowCl[NMAX];
__device__ float g_rowR[NMAX];

// ---------------------------------------------------------------------------
__global__ void k_zero() {
    if (threadIdx.x < CLS_MAX) g_cnt[threadIdx.x] = 0;
}

// One block (128 threads) per row: L2-normalize + integer class histogram.
__global__ void k_normalize(const float* __restrict__ x, const int* __restrict__ tgt) {
    int row = blockIdx.x;
    int t = threadIdx.x;
    float v = x[row * KD + t];
    float ss = v * v;
    #pragma unroll
    for (int o = 16; o; o >>= 1) ss += __shfl_xor_sync(0xffffffffu, ss, o);
    __shared__ float w[4];
    if ((t & 31) == 0) w[t >> 5] = ss;
    __syncthreads();
    float tot = w[0] + w[1] + w[2] + w[3];
    float nrm = fmaxf(sqrtf(tot), 1e-12f);
    g_feats[row * KD + t] = v / nrm;
    if (t == 0) atomicAdd(&g_cnt[tgt[row]], 1);   // integer atomic: deterministic
}

// One warp per row: cross entropy (C <= 32).
__global__ void k_ce(const float* __restrict__ pred, const int* __restrict__ tgt,
                     int N, int C) {
    int row  = (int)((blockIdx.x * blockDim.x + threadIdx.x) >> 5);
    int lane = threadIdx.x & 31;
    if (row >= N) return;
    float v = (lane < C) ? pred[row * C + lane] : -1e30f;
    float mx = v;
    #pragma unroll
    for (int o = 16; o; o >>= 1) mx = fmaxf(mx, __shfl_xor_sync(0xffffffffu, mx, o));
    float e = (lane < C) ? __expf(v - mx) : 0.f;
    #pragma unroll
    for (int o = 16; o; o >>= 1) e += __shfl_xor_sync(0xffffffffu, e, o);
    int tg = tgt[row];
    float vt = __shfl_sync(0xffffffffu, v, tg);
    if (lane == 0) g_rowCe[row] = vt - mx - logf(e);   // log p(target)
}

// ---------------------------------------------------------------------------
// Main fused pass: per block, TM=16 rows. Threads: jj = t&127 (column in
// j-tile), mh = t>>7 selects 8-row half. Each thread keeps 8 dot accumulators
// plus online-softmax state for 8 rows over its private j-subset; merged at
// the end via shfl + shared.
__global__ void __launch_bounds__(256) k_main(const int* __restrict__ tgt, int N) {
    extern __shared__ float sm[];
    float* s_i  = sm;                        // [TM][SJP]
    float* s_j  = sm + TM * SJP;             // [TN][SJP]
    int*   s_lab = (int*)(s_j + TN * SJP);   // [TN]
    __shared__ int s_ilab[TM];

    int t  = threadIdx.x;
    int jj = t & (TN - 1);
    int mh = t >> 7;                         // 0..1 -> rows mh*8 .. mh*8+7
    int rowBase = blockIdx.x * TM;

    for (int idx = t; idx < TM * KD / 4; idx += 256) {
        int r = idx >> 5, c4 = idx & 31;
        float4 v = *(const float4*)&g_feats[(rowBase + r) * KD + c4 * 4];
        *(float4*)&s_i[r * SJP + c4 * 4] = v;
    }
    if (t < TM) s_ilab[t] = tgt[rowBase + t];
    __syncthreads();

    int ilab[8];
    #pragma unroll
    for (int m = 0; m < 8; m++) ilab[m] = s_ilab[mh * 8 + m];

    // per-row online state (this thread's j subset):
    // mx  : running max of G (full row, for cl)
    // sE  : sum exp((G - mx)*10) over same-label j != i
    // bmx : running max of max(0, G*20 over diff-label)  (init 0 = the "zeros" in B)
    // rs  : sum exp(G*20 - bmx) over diff-label j
    // ssm : sum of G over same-label j != i
    float mx[8], sE[8], bmx[8], rs[8], ssm[8];
    #pragma unroll
    for (int m = 0; m < 8; m++) { mx[m] = -1e30f; sE[m] = 0.f; bmx[m] = 0.f; rs[m] = 0.f; ssm[m] = 0.f; }

    for (int j0 = 0; j0 < N; j0 += TN) {
        __syncthreads();
        for (int idx = t; idx < TN * KD / 4; idx += 256) {
            int r = idx >> 5, c4 = idx & 31;
            float4 v = *(const float4*)&g_feats[(j0 + r) * KD + c4 * 4];
            *(float4*)&s_j[r * SJP + c4 * 4] = v;
        }
        if (t < TN) s_lab[t] = tgt[j0 + t];
        __syncthreads();

        float a[8];
        #pragma unroll
        for (int m = 0; m < 8; m++) a[m] = 0.f;
        const float* fj = &s_j[jj * SJP];
        #pragma unroll
        for (int k4 = 0; k4 < KD / 4; k4++) {
            float4 b = *(const float4*)&fj[k4 * 4];
            #pragma unroll
            for (int m = 0; m < 8; m++) {
                float4 ai = *(const float4*)&s_i[(mh * 8 + m) * SJP + k4 * 4];
                a[m] = fmaf(ai.x, b.x, a[m]);
                a[m] = fmaf(ai.y, b.y, a[m]);
                a[m] = fmaf(ai.z, b.z, a[m]);
                a[m] = fmaf(ai.w, b.w, a[m]);
            }
        }

        int jg   = j0 + jj;
        int labj = s_lab[jj];
        #pragma unroll
        for (int m = 0; m < 8; m++) {
            float g = a[m];
            if (g > mx[m]) { sE[m] *= __expf((mx[m] - g) * 10.f); mx[m] = g; }
            if (labj == ilab[m]) {
                if (jg != rowBase + mh * 8 + m) {
                    sE[m]  += __expf((g - mx[m]) * 10.f);
                    ssm[m] += g;
                }
            } else {
                float b2 = g * 20.f;
                if (b2 > bmx[m]) { rs[m] *= __expf(bmx[m] - b2); bmx[m] = b2; }
                rs[m] += __expf(b2 - bmx[m]);
            }
        }
    }

    // warp-level merge (all 32 lanes of a warp share the same 8 rows)
    #pragma unroll
    for (int m = 0; m < 8; m++) {
        #pragma unroll
        for (int o = 16; o; o >>= 1) {
            float omx = __shfl_xor_sync(0xffffffffu, mx[m], o);
            float osE = __shfl_xor_sync(0xffffffffu, sE[m], o);
            float M = fmaxf(mx[m], omx);
            sE[m] = sE[m] * __expf((mx[m] - M) * 10.f) + osE * __expf((omx - M) * 10.f);
            mx[m] = M;
            float ob  = __shfl_xor_sync(0xffffffffu, bmx[m], o);
            float orr = __shfl_xor_sync(0xffffffffu, rs[m], o);
            float B = fmaxf(bmx[m], ob);
            rs[m] = rs[m] * __expf(bmx[m] - B) + orr * __expf(ob - B);
            bmx[m] = B;
            ssm[m] += __shfl_xor_sync(0xffffffffu, ssm[m], o);
        }
    }

    __syncthreads();
    float* buf = s_j;   // reuse: [8 warps][8 m][5 stats]
    int warp = t >> 5, lane = t & 31;
    if (lane == 0) {
        #pragma unroll
        for (int m = 0; m < 8; m++) {
            float* p = &buf[(warp * 8 + m) * 5];
            p[0] = mx[m]; p[1] = sE[m]; p[2] = bmx[m]; p[3] = rs[m]; p[4] = ssm[m];
        }
    }
    __syncthreads();

    if (t < TM) {   // one thread finalizes each row (merges 4 warp partials)
        int mh2 = t >> 3, m2 = t & 7;
        float M = -1e30f, S = 0.f, B = 0.f, R = 0.f, SS = 0.f;
        for (int w = mh2 * 4; w < mh2 * 4 + 4; w++) {
            const float* p = &buf[(w * 8 + m2) * 5];
            float m1 = p[0], s1 = p[1], b1 = p[2], r1 = p[3];
            float nM = fmaxf(M, m1);
            S = S * __expf((M - nM) * 10.f) + s1 * __expf((m1 - nM) * 10.f);
            M = nM;
            float nB = fmaxf(B, b1);
            R = R * __expf(B - nB) + r1 * __expf(b1 - nB);
            B = nB;
            SS += p[4];
        }
        int rowg = rowBase + t;
        int lab  = s_ilab[t];
        int cnt  = g_cnt[lab];
        float clc = 0.f;
        int msum = cnt - 1;
        if (msum > 0) {
            // mean over same-label j!=i of log_prob = (sum(logits) - msum*max)/msum - log(E+eps)
            clc = (SS * 10.f - (float)msum * (M * 10.f)) / (float)msum
                  - logf(S + 1e-12f);
        }
        g_rowCl[rowg] = clc;
        // r_j = sum_diff exp(B - bmax) + n_same * exp(-bmax)   (same entries of B are 0)
        g_rowR[rowg] = R + (float)cnt * __expf(-B);
    }
}

// ---------------------------------------------------------------------------
// Final reduction: fixed-order (deterministic) tree reductions, then the
// class-collapsed triple loss on thread 0.
__global__ void k_final(const int* __restrict__ tgt, float* __restrict__ out,
                        int N, int C) {
    __shared__ float sred[256];
    __shared__ float classR[CLS_MAX];
    int t = threadIdx.x;

    float ce = 0.f, cl = 0.f;
    for (int i = t; i < N; i += 256) { ce += g_rowCe[i]; cl += g_rowCl[i]; }

    sred[t] = ce; __syncthreads();
    for (int s = 128; s; s >>= 1) { if (t < s) sred[t] += sred[t + s]; __syncthreads(); }
    float ceSum = sred[0]; __syncthreads();

    sred[t] = cl; __syncthreads();
    for (int s = 128; s; s >>= 1) { if (t < s) sred[t] += sred[t + s]; __syncthreads(); }
    float clSum = sred[0]; __syncthreads();

    for (int c = 0; c < C; c++) {
        float p = 0.f;
        for (int i = t; i < N; i += 256) p += (tgt[i] == c) ? g_rowR[i] : 0.f;
        sred[t] = p; __syncthreads();
        for (int s = 128; s; s >>= 1) { if (t < s) sred[t] += sred[t + s]; __syncthreads(); }
        if (t == 0) classR[c] = sred[0];
        __syncthreads();
    }

    if (t == 0) {
        float totalR = 0.f;
        long long total_c = 0;
        for (int c = 0; c < C; c++) {
            totalR += classR[c];
            long long cc = g_cnt[c];
            total_c += cc * (long long)(N - (int)cc);
        }
        bool all_zero = true;
        for (int c = 0; c < C; c++) {
            int cc = g_cnt[c];
            if (cc > 0) {
                long long ns = total_c - (long long)cc * (N - cc);
                if (ns != 0) { all_zero = false; break; }
            }
        }
        float tripleSum = 0.f;
        for (int c = 0; c < C; c++) {
            int cc = g_cnt[c];
            if (cc == 0) continue;
            float S = (N - cc > 0) ? (totalR - classR[c] + (float)cc * (float)N) : 0.f;
            long long ns = total_c - (long long)cc * (N - cc);
            float x = all_zero ? S : S / ((ns == 0) ? 1.0f : (float)ns);
            tripleSum += (float)cc * logf(x + 1e-12f);
        }
        float ce_loss = -ceSum / (float)N;
        float cl_loss = -clSum / (float)N;
        float triple  = tripleSum / (float)N;   // = -mean(logp)
        out[0] = 0.5f * ce_loss + 0.5f * cl_loss + 0.25f * triple;
    }
}

// ---------------------------------------------------------------------------
extern "C" void kernel_launch(void* const* d_in, const int* in_sizes, int n_in,
                              void* d_out, int out_size) {
    const float* cls  = (const float*)d_in[0];
    const float* pred = (const float*)d_in[1];
    const int*   tgt  = (const int*)d_in[2];
    int N = in_sizes[2];
    int C = in_sizes[1] / N;
    float* out = (float*)d_out;

    k_zero<<<1, CLS_MAX>>>();
    k_normalize<<<N, KD>>>(cls, tgt);
    k_ce<<<(N + 7) / 8, 256>>>(pred, tgt, N, C);

    int smem = (TM + TN) * SJP * (int)sizeof(float) + TN * (int)sizeof(int);
    cudaFuncSetAttribute(k_main, cudaFuncAttributeMaxDynamicSharedMemorySize, smem);
    k_main<<<N / TM, 256, smem>>>(tgt, N);

    k_final<<<1, 256>>>(tgt, out, N, C);
}

// round 2
// speedup vs baseline: 1.8636x; 1.8636x over previous
#include <cuda_runtime.h>
#include <math.h>

// SupConLoss fused, register-tiled Gram pass for GB300 (sm_103a).
// out = 0.5*ce + 0.5*cl + 0.25*triple   (ALPHA = 0.5)
// Key identity: feats are L2-normalized so every Gram entry g in [-1,1].
// => use FIXED softmax shifts: exp((g-1)*10) for cl, exp((g-1)*20) for triple.
//    Partial sums are then plain adds (mergeable, deterministic), and the
//    per-row max for the triple rescale is a simple fmaxf over g.

#define KD   128
#define NN   4096
#define CLS_MAX 64
#define NJT  32           // 4096 / 128 j-tiles

__device__ __align__(16) float g_featsT[KD * NN];   // [k][row]
__device__ int    g_cnt[CLS_MAX];
__device__ float  g_rowCe[NN];
__device__ float  g_rowCl[NN];
__device__ float  g_rowR[NN];
__device__ float4 g_part[NN * NJT];                 // [row][jt] : sE, ssm, rs, maxg

// ---------------------------------------------------------------------------
__global__ void k_zero() {
    if (threadIdx.x < CLS_MAX) g_cnt[threadIdx.x] = 0;
}

// One block (128 threads) per row: L2-normalize, write transposed, histogram.
__global__ void k_normalize(const float* __restrict__ x, const int* __restrict__ tgt) {
    int row = blockIdx.x;
    int t = threadIdx.x;
    float v = x[row * KD + t];
    float ss = v * v;
    #pragma unroll
    for (int o = 16; o; o >>= 1) ss += __shfl_xor_sync(0xffffffffu, ss, o);
    __shared__ float w[4];
    if ((t & 31) == 0) w[t >> 5] = ss;
    __syncthreads();
    float tot = w[0] + w[1] + w[2] + w[3];
    float nrm = fmaxf(sqrtf(tot), 1e-12f);
    g_featsT[t * NN + row] = v / nrm;
    if (t == 0) atomicAdd(&g_cnt[tgt[row]], 1);
}

// One warp per row: cross entropy (C <= 32).
__global__ void k_ce(const float* __restrict__ pred, const int* __restrict__ tgt,
                     int N, int C) {
    int row  = (int)((blockIdx.x * blockDim.x + threadIdx.x) >> 5);
    int lane = threadIdx.x & 31;
    if (row >= N) return;
    float v = (lane < C) ? pred[row * C + lane] : -1e30f;
    float mx = v;
    #pragma unroll
    for (int o = 16; o; o >>= 1) mx = fmaxf(mx, __shfl_xor_sync(0xffffffffu, mx, o));
    float e = (lane < C) ? __expf(v - mx) : 0.f;
    #pragma unroll
    for (int o = 16; o; o >>= 1) e += __shfl_xor_sync(0xffffffffu, e, o);
    int tg = tgt[row];
    float vt = __shfl_sync(0xffffffffu, v, tg);
    if (lane == 0) g_rowCe[row] = vt - mx - logf(e);
}

// ---------------------------------------------------------------------------
// Main pass: grid = 64 m-tiles x 32 j-tiles = 2048 blocks, 128 threads.
// Block tile 64(M) x 128(N), micro-tile 8x8 per thread over K=128.
// Shared: s_a [k][64] (32KB), s_b [k][128] (64KB) -> 2 blocks/SM.
__global__ void __launch_bounds__(128) k_main(const int* __restrict__ tgt) {
    extern __shared__ float sm[];
    float* s_a = sm;                 // 128*64
    float* s_b = sm + 8192;          // 128*128
    int*   s_il = (int*)(sm + 8192 + 16384);        // 64
    int*   s_jl = s_il + 64;                        // 128

    int tid = threadIdx.x;
    int mt = blockIdx.x >> 5, jt = blockIdx.x & 31;
    int rowBase = mt * 64, jBase = jt * 128;

    // load s_a: 64 rows of g_featsT tile -> [k][m]
    #pragma unroll
    for (int i = tid; i < 2048; i += 128) {
        int k = i >> 4, c = i & 15;
        float4 v = *(const float4*)&g_featsT[k * NN + rowBase + c * 4];
        *(float4*)&s_a[k * 64 + c * 4] = v;
    }
    #pragma unroll
    for (int i = tid; i < 4096; i += 128) {
        int k = i >> 5, c = i & 31;
        float4 v = *(const float4*)&g_featsT[k * NN + jBase + c * 4];
        *(float4*)&s_b[k * 128 + c * 4] = v;
    }
    if (tid < 64) s_il[tid] = tgt[rowBase + tid];
    s_jl[tid] = tgt[jBase + tid];
    __syncthreads();

    int tr = tid & 7, tc = tid >> 3;

    float acc[8][8];
    #pragma unroll
    for (int q = 0; q < 8; q++)
        #pragma unroll
        for (int p = 0; p < 8; p++) acc[q][p] = 0.f;

    #pragma unroll 4
    for (int k = 0; k < KD; k++) {
        float4 a0 = *(const float4*)&s_a[k * 64 + tr * 4];
        float4 a1 = *(const float4*)&s_a[k * 64 + 32 + tr * 4];
        float4 b0 = *(const float4*)&s_b[k * 128 + tc * 4];
        float4 b1 = *(const float4*)&s_b[k * 128 + 64 + tc * 4];
        float am[8] = {a0.x, a0.y, a0.z, a0.w, a1.x, a1.y, a1.z, a1.w};
        float bn[8] = {b0.x, b0.y, b0.z, b0.w, b1.x, b1.y, b1.z, b1.w};
        #pragma unroll
        for (int q = 0; q < 8; q++)
            #pragma unroll
            for (int p = 0; p < 8; p++)
                acc[q][p] = fmaf(am[q], bn[p], acc[q][p]);
    }

    // micro-tile row/col indices
    int mr[8], nc[8];
    #pragma unroll
    for (int q = 0; q < 8; q++) mr[q] = tr * 4 + (q & 3) + ((q >> 2) << 5);
    #pragma unroll
    for (int p = 0; p < 8; p++) nc[p] = tc * 4 + (p & 3) + ((p >> 2) << 6);

    int ilab[8];
    #pragma unroll
    for (int q = 0; q < 8; q++) ilab[q] = s_il[mr[q]];

    float sE[8], ssm[8], rs[8], bmx[8];
    #pragma unroll
    for (int q = 0; q < 8; q++) { sE[q] = 0.f; ssm[q] = 0.f; rs[q] = 0.f; bmx[q] = -2.f; }

    #pragma unroll
    for (int p = 0; p < 8; p++) {
        int jlab = s_jl[nc[p]];
        int jg = jBase + nc[p];
        #pragma unroll
        for (int q = 0; q < 8; q++) {
            float g = acc[q][p];
            float e10 = __expf(fmaf(g, 10.f, -10.f));
            float e20 = e10 * e10;
            bool same = (jlab == ilab[q]);
            if (same) {
                if (jg != rowBase + mr[q]) { sE[q] += e10; ssm[q] += g; }
            } else {
                rs[q] += e20;
                bmx[q] = fmaxf(bmx[q], g);
            }
        }
    }

    // cross-thread (tc) reduction per row via shared (padded stride 17 float4)
    __syncthreads();
    float4* part = (float4*)s_b;     // 64*17 float4 = 17KB, fits
    #pragma unroll
    for (int q = 0; q < 8; q++)
        part[mr[q] * 17 + tc] = make_float4(sE[q], ssm[q], rs[q], bmx[q]);
    __syncthreads();

    if (tid < 64) {
        float a = 0.f, b = 0.f, c = 0.f, d = -2.f;
        #pragma unroll
        for (int t = 0; t < 16; t++) {
            float4 v = part[tid * 17 + t];
            a += v.x; b += v.y; c += v.z; d = fmaxf(d, v.w);
        }
        g_part[(rowBase + tid) * NJT + jt] = make_float4(a, b, c, d);
    }
}

// ---------------------------------------------------------------------------
// One warp per row: merge 32 j-tile partials, finalize cl row + r_j.
__global__ void k_reduce(const int* __restrict__ tgt) {
    int row  = blockIdx.x * 8 + (threadIdx.x >> 5);
    int lane = threadIdx.x & 31;
    float4 v = g_part[row * NJT + lane];
    #pragma unroll
    for (int o = 16; o; o >>= 1) {
        v.x += __shfl_xor_sync(0xffffffffu, v.x, o);
        v.y += __shfl_xor_sync(0xffffffffu, v.y, o);
        v.z += __shfl_xor_sync(0xffffffffu, v.z, o);
        v.w = fmaxf(v.w, __shfl_xor_sync(0xffffffffu, v.w, o));
    }
    if (lane == 0) {
        int cnt = g_cnt[tgt[row]];
        int msum = cnt - 1;
        float clc = 0.f;
        if (msum > 0)
            clc = v.y * 10.f / (float)msum - 10.f - logf(v.x + 1e-12f);
        g_rowCl[row] = clc;
        // r_row = sum_diff exp(20g - Bmax) + n_same * exp(-Bmax),
        // Bmax = max(0, 20*maxg_diff); v.z has shift 20 baked in.
        float Bmax = fmaxf(0.f, v.w * 20.f);
        g_rowR[row] = v.z * expf(20.f - Bmax) + (float)cnt * expf(-Bmax);
    }
}

// ---------------------------------------------------------------------------
__global__ void k_final(const int* __restrict__ tgt, float* __restrict__ out,
                        int N, int C) {
    __shared__ float sred[256];
    __shared__ float classR[CLS_MAX];
    int t = threadIdx.x;
    int warp = t >> 5, lane = t & 31;

    float ce = 0.f, cl = 0.f;
    for (int i = t; i < N; i += 256) { ce += g_rowCe[i]; cl += g_rowCl[i]; }

    sred[t] = ce; __syncthreads();
    for (int s = 128; s; s >>= 1) { if (t < s) sred[t] += sred[t + s]; __syncthreads(); }
    float ceSum = sred[0]; __syncthreads();

    sred[t] = cl; __syncthreads();
    for (int s = 128; s; s >>= 1) { if (t < s) sred[t] += sred[t + s]; __syncthreads(); }
    float clSum = sred[0]; __syncthreads();

    for (int c = warp; c < C; c += 8) {
        float p = 0.f;
        for (int i = lane; i < N; i += 32) p += (tgt[i] == c) ? g_rowR[i] : 0.f;
        #pragma unroll
        for (int o = 16; o; o >>= 1) p += __shfl_xor_sync(0xffffffffu, p, o);
        if (lane == 0) classR[c] = p;
    }
    __syncthreads();

    if (t == 0) {
        float totalR = 0.f;
        long long total_c = 0;
        for (int c = 0; c < C; c++) {
            totalR += classR[c];
            long long cc = g_cnt[c];
            total_c += cc * (long long)(N - (int)cc);
        }
        bool all_zero = true;
        for (int c = 0; c < C; c++) {
            int cc = g_cnt[c];
            if (cc > 0) {
                long long ns = total_c - (long long)cc * (N - cc);
                if (ns != 0) { all_zero = false; break; }
            }
        }
        float tripleSum = 0.f;
        for (int c = 0; c < C; c++) {
            int cc = g_cnt[c];
            if (cc == 0) continue;
            float S = (N - cc > 0) ? (totalR - classR[c] + (float)cc * (float)N) : 0.f;
            long long ns = total_c - (long long)cc * (N - cc);
            float x = all_zero ? S : S / ((ns == 0) ? 1.0f : (float)ns);
            tripleSum += (float)cc * logf(x + 1e-12f);
        }
        float ce_loss = -ceSum / (float)N;
        float cl_loss = -clSum / (float)N;
        float triple  = tripleSum / (float)N;
        out[0] = 0.5f * ce_loss + 0.5f * cl_loss + 0.25f * triple;
    }
}

// ---------------------------------------------------------------------------
extern "C" void kernel_launch(void* const* d_in, const int* in_sizes, int n_in,
                              void* d_out, int out_size) {
    const float* cls  = (const float*)d_in[0];
    const float* pred = (const float*)d_in[1];
    const int*   tgt  = (const int*)d_in[2];
    int N = in_sizes[2];
    int C = in_sizes[1] / N;
    float* out = (float*)d_out;

    k_zero<<<1, CLS_MAX>>>();
    k_normalize<<<N, KD>>>(cls, tgt);
    k_ce<<<(N + 7) / 8, 256>>>(pred, tgt, N, C);

    int smem = (128 * 64 + 128 * 128) * (int)sizeof(float) + (64 + 128) * (int)sizeof(int);
    cudaFuncSetAttribute(k_main, cudaFuncAttributeMaxDynamicSharedMemorySize, smem);
    k_main<<<(N / 64) * NJT, 128, smem>>>(tgt);

    k_reduce<<<N / 8, 256>>>(tgt);
    k_final<<<1, 256>>>(tgt, out, N, C);
}

// round 3
// speedup vs baseline: 2.6928x; 1.4450x over previous
#include <cuda_runtime.h>
#include <math.h>

// SupConLoss fused, symmetric register-tiled Gram pass for GB300 (sm_103a).
// out = 0.5*ce + 0.5*cl + 0.25*triple   (ALPHA = 0.5)
// feats are L2-normalized => Gram entries in [-1,1] => fixed softmax shifts
// exp((g-1)*10) / exp((g-1)*20): partials are plain sums (mergeable, deterministic).
// Symmetry: only upper-triangular 128x128 tiles computed; off-diagonal blocks
// emit BOTH row-stats (rows of mt-tile) and col-stats (rows of jt-tile).

#define KD   128
#define NN   4096
#define CLS_MAX 64
#define NJT  32           // 4096 / 128 tiles per dimension

__device__ __align__(16) float g_featsT[KD * NN];   // [k][row]
__device__ int    g_cnt[CLS_MAX];
__device__ float  g_rowCe[NN];
__device__ float  g_rowCl[NN];
__device__ float  g_rowR[NN];
__device__ float4 g_part[NN * NJT];                 // [row][slot] : sE, ssm, rs, maxg

// ---------------------------------------------------------------------------
__global__ void k_zero() {
    if (threadIdx.x < CLS_MAX) g_cnt[threadIdx.x] = 0;
}

// 32 rows per block (256 threads): normalize + coalesced transposed store.
__global__ void __launch_bounds__(256) k_normalize(const float* __restrict__ x,
                                                   const int* __restrict__ tgt) {
    __shared__ float s[32 * 129];
    int tid = threadIdx.x;
    int r = tid >> 3, l8 = tid & 7;               // 8 threads per row
    int row = blockIdx.x * 32 + r;

    float v[16];
    const float4* xr = (const float4*)&x[row * KD + l8 * 16];
    float ss = 0.f;
    #pragma unroll
    for (int i = 0; i < 4; i++) {
        float4 q = xr[i];
        v[i * 4 + 0] = q.x; v[i * 4 + 1] = q.y; v[i * 4 + 2] = q.z; v[i * 4 + 3] = q.w;
        ss += q.x * q.x + q.y * q.y + q.z * q.z + q.w * q.w;
    }
    #pragma unroll
    for (int o = 4; o; o >>= 1) ss += __shfl_xor_sync(0xffffffffu, ss, o);
    float inv = 1.f / fmaxf(sqrtf(ss), 1e-12f);
    #pragma unroll
    for (int i = 0; i < 16; i++) s[r * 129 + l8 * 16 + i] = v[i] * inv;
    if (l8 == 0) atomicAdd(&g_cnt[tgt[row]], 1);
    __syncthreads();

    // transposed write: consecutive threads -> consecutive rows (coalesced 128B)
    #pragma unroll
    for (int i = 0; i < 16; i++) {
        int idx = tid + i * 256;
        int rr = idx & 31, k = idx >> 5;
        g_featsT[k * NN + blockIdx.x * 32 + rr] = s[rr * 129 + k];
    }
}

// One warp per row: cross entropy (C <= 32).
__global__ void k_ce(const float* __restrict__ pred, const int* __restrict__ tgt,
                     int N, int C) {
    int row  = (int)((blockIdx.x * blockDim.x + threadIdx.x) >> 5);
    int lane = threadIdx.x & 31;
    if (row >= N) return;
    float v = (lane < C) ? pred[row * C + lane] : -1e30f;
    float mx = v;
    #pragma unroll
    for (int o = 16; o; o >>= 1) mx = fmaxf(mx, __shfl_xor_sync(0xffffffffu, mx, o));
    float e = (lane < C) ? __expf(v - mx) : 0.f;
    #pragma unroll
    for (int o = 16; o; o >>= 1) e += __shfl_xor_sync(0xffffffffu, e, o);
    int tg = tgt[row];
    float vt = __shfl_sync(0xffffffffu, v, tg);
    if (lane == 0) g_rowCe[row] = vt - mx - logf(e);
}

// ---------------------------------------------------------------------------
// Main pass: 528 triangular blocks (mt<=jt), 256 threads, tile 128x128,
// micro-tile 8x8/thread, K chunked by 32 (4 chunks).
// Shared union: tiles (32KB) overlapped by epilogue partials (34.8KB) + labels.
#define SMEM_MAIN (35840 + 1024)

__global__ void __launch_bounds__(256, 2) k_main(const int* __restrict__ tgt) {
    extern __shared__ float sm[];
    float*  s_a  = sm;                       // [32][128]
    float*  s_b  = sm + 32 * 128;            // [32][128]
    float4* part = (float4*)sm;              // [128][17] (epilogue, overlaps tiles)
    int*    s_il = (int*)(sm + 35840 / 4);   // 128
    int*    s_jl = s_il + 128;               // 128

    int tid = threadIdx.x;
    // triangular block index -> (mt, jt)
    int b = blockIdx.x, mt = 0;
    while (b >= NJT - mt) { b -= NJT - mt; mt++; }
    int jt = mt + b;
    int rowBase = mt * 128, jBase = jt * 128;

    if (tid < 128) s_il[tid] = tgt[rowBase + tid];
    else           s_jl[tid - 128] = tgt[jBase + (tid - 128)];

    int tr = tid & 15, tc = tid >> 4;

    float acc[8][8];
    #pragma unroll
    for (int q = 0; q < 8; q++)
        #pragma unroll
        for (int p = 0; p < 8; p++) acc[q][p] = 0.f;

    for (int kc = 0; kc < 4; kc++) {
        __syncthreads();
        #pragma unroll
        for (int i = 0; i < 4; i++) {
            int idx = tid + i * 256;             // 1024 float4 per tile
            int k = idx >> 5, c4 = idx & 31;
            *(float4*)&s_a[k * 128 + c4 * 4] =
                *(const float4*)&g_featsT[(kc * 32 + k) * NN + rowBase + c4 * 4];
            *(float4*)&s_b[k * 128 + c4 * 4] =
                *(const float4*)&g_featsT[(kc * 32 + k) * NN + jBase + c4 * 4];
        }
        __syncthreads();
        #pragma unroll 8
        for (int k = 0; k < 32; k++) {
            float4 a0 = *(const float4*)&s_a[k * 128 + tr * 4];
            float4 a1 = *(const float4*)&s_a[k * 128 + 64 + tr * 4];
            float4 b0 = *(const float4*)&s_b[k * 128 + tc * 4];
            float4 b1 = *(const float4*)&s_b[k * 128 + 64 + tc * 4];
            float am[8] = {a0.x, a0.y, a0.z, a0.w, a1.x, a1.y, a1.z, a1.w};
            float bn[8] = {b0.x, b0.y, b0.z, b0.w, b1.x, b1.y, b1.z, b1.w};
            #pragma unroll
            for (int q = 0; q < 8; q++)
                #pragma unroll
                for (int p = 0; p < 8; p++)
                    acc[q][p] = fmaf(am[q], bn[p], acc[q][p]);
        }
    }
    __syncthreads();   // tiles dead; smem reused for partials

    int mr[8], nc[8];
    #pragma unroll
    for (int q = 0; q < 8; q++) mr[q] = tr * 4 + (q & 3) + ((q >> 2) << 6);
    #pragma unroll
    for (int p = 0; p < 8; p++) nc[p] = tc * 4 + (p & 3) + ((p >> 2) << 6);

    int ilab[8], jlab[8];
    #pragma unroll
    for (int q = 0; q < 8; q++) ilab[q] = s_il[mr[q]];
    #pragma unroll
    for (int p = 0; p < 8; p++) jlab[p] = s_jl[nc[p]];

    // ---- row stats (rows rowBase+mr over columns jBase+nc) ----
    {
        float sE[8], ssm[8], rs[8], bmx[8];
        #pragma unroll
        for (int q = 0; q < 8; q++) { sE[q] = 0.f; ssm[q] = 0.f; rs[q] = 0.f; bmx[q] = -2.f; }
        #pragma unroll
        for (int p = 0; p < 8; p++) {
            int jg = jBase + nc[p];
            #pragma unroll
            for (int q = 0; q < 8; q++) {
                float g = acc[q][p];
                float e10 = __expf(fmaf(g, 10.f, -10.f));
                if (jlab[p] == ilab[q]) {
                    if (jg != rowBase + mr[q]) { sE[q] += e10; ssm[q] += g; }
                } else {
                    rs[q] += e10 * e10;
                    bmx[q] = fmaxf(bmx[q], g);
                }
            }
        }
        #pragma unroll
        for (int q = 0; q < 8; q++)
            part[mr[q] * 17 + tc] = make_float4(sE[q], ssm[q], rs[q], bmx[q]);
        __syncthreads();
        if (tid < 128) {
            float a = 0.f, bb = 0.f, c = 0.f, d = -2.f;
            #pragma unroll
            for (int t = 0; t < 16; t++) {
                float4 v = part[tid * 17 + t];
                a += v.x; bb += v.y; c += v.z; d = fmaxf(d, v.w);
            }
            g_part[(rowBase + tid) * NJT + jt] = make_float4(a, bb, c, d);
        }
    }

    // ---- col stats (rows jBase+nc over columns rowBase+mr), off-diag only ----
    if (mt != jt) {
        __syncthreads();
        float sE[8], ssm[8], rs[8], bmx[8];
        #pragma unroll
        for (int p = 0; p < 8; p++) { sE[p] = 0.f; ssm[p] = 0.f; rs[p] = 0.f; bmx[p] = -2.f; }
        #pragma unroll
        for (int q = 0; q < 8; q++) {
            #pragma unroll
            for (int p = 0; p < 8; p++) {
                float g = acc[q][p];
                float e10 = __expf(fmaf(g, 10.f, -10.f));
                if (jlab[p] == ilab[q]) {
                    sE[p] += e10; ssm[p] += g;      // mt!=jt: never the diagonal
                } else {
                    rs[p] += e10 * e10;
                    bmx[p] = fmaxf(bmx[p], g);
                }
            }
        }
        #pragma unroll
        for (int p = 0; p < 8; p++)
            part[nc[p] * 17 + tr] = make_float4(sE[p], ssm[p], rs[p], bmx[p]);
        __syncthreads();
        if (tid < 128) {
            float a = 0.f, bb = 0.f, c = 0.f, d = -2.f;
            #pragma unroll
            for (int t = 0; t < 16; t++) {
                float4 v = part[tid * 17 + t];
                a += v.x; bb += v.y; c += v.z; d = fmaxf(d, v.w);
            }
            g_part[(jBase + tid) * NJT + mt] = make_float4(a, bb, c, d);
        }
    }
}

// ---------------------------------------------------------------------------
// One warp per row: merge 32 tile partials, finalize cl row + r_j.
__global__ void k_reduce(const int* __restrict__ tgt) {
    int row  = blockIdx.x * 8 + (threadIdx.x >> 5);
    int lane = threadIdx.x & 31;
    float4 v = g_part[row * NJT + lane];
    #pragma unroll
    for (int o = 16; o; o >>= 1) {
        v.x += __shfl_xor_sync(0xffffffffu, v.x, o);
        v.y += __shfl_xor_sync(0xffffffffu, v.y, o);
        v.z += __shfl_xor_sync(0xffffffffu, v.z, o);
        v.w = fmaxf(v.w, __shfl_xor_sync(0xffffffffu, v.w, o));
    }
    if (lane == 0) {
        int cnt = g_cnt[tgt[row]];
        int msum = cnt - 1;
        float clc = 0.f;
        if (msum > 0)
            clc = v.y * 10.f / (float)msum - 10.f - logf(v.x + 1e-12f);
        g_rowCl[row] = clc;
        float Bmax = fmaxf(0.f, v.w * 20.f);
        g_rowR[row] = v.z * expf(20.f - Bmax) + (float)cnt * expf(-Bmax);
    }
}

// ---------------------------------------------------------------------------
__global__ void k_final(const int* __restrict__ tgt, float* __restrict__ out,
                        int N, int C) {
    __shared__ float sred[256];
    __shared__ float classR[CLS_MAX];
    int t = threadIdx.x;
    int warp = t >> 5, lane = t & 31;

    float ce = 0.f, cl = 0.f;
    for (int i = t; i < N; i += 256) { ce += g_rowCe[i]; cl += g_rowCl[i]; }

    sred[t] = ce; __syncthreads();
    for (int s = 128; s; s >>= 1) { if (t < s) sred[t] += sred[t + s]; __syncthreads(); }
    float ceSum = sred[0]; __syncthreads();

    sred[t] = cl; __syncthreads();
    for (int s = 128; s; s >>= 1) { if (t < s) sred[t] += sred[t + s]; __syncthreads(); }
    float clSum = sred[0]; __syncthreads();

    for (int c = warp; c < C; c += 8) {
        float p = 0.f;
        for (int i = lane; i < N; i += 32) p += (tgt[i] == c) ? g_rowR[i] : 0.f;
        #pragma unroll
        for (int o = 16; o; o >>= 1) p += __shfl_xor_sync(0xffffffffu, p, o);
        if (lane == 0) classR[c] = p;
    }
    __syncthreads();

    if (t == 0) {
        float totalR = 0.f;
        long long total_c = 0;
        for (int c = 0; c < C; c++) {
            totalR += classR[c];
            long long cc = g_cnt[c];
            total_c += cc * (long long)(N - (int)cc);
        }
        bool all_zero = true;
        for (int c = 0; c < C; c++) {
            int cc = g_cnt[c];
            if (cc > 0) {
                long long ns = total_c - (long long)cc * (N - cc);
                if (ns != 0) { all_zero = false; break; }
            }
        }
        float tripleSum = 0.f;
        for (int c = 0; c < C; c++) {
            int cc = g_cnt[c];
            if (cc == 0) continue;
            float S = (N - cc > 0) ? (totalR - classR[c] + (float)cc * (float)N) : 0.f;
            long long ns = total_c - (long long)cc * (N - cc);
            float x = all_zero ? S : S / ((ns == 0) ? 1.0f : (float)ns);
            tripleSum += (float)cc * logf(x + 1e-12f);
        }
        float ce_loss = -ceSum / (float)N;
        float cl_loss = -clSum / (float)N;
        float triple  = tripleSum / (float)N;
        out[0] = 0.5f * ce_loss + 0.5f * cl_loss + 0.25f * triple;
    }
}

// ---------------------------------------------------------------------------
extern "C" void kernel_launch(void* const* d_in, const int* in_sizes, int n_in,
                              void* d_out, int out_size) {
    const float* cls  = (const float*)d_in[0];
    const float* pred = (const float*)d_in[1];
    const int*   tgt  = (const int*)d_in[2];
    int N = in_sizes[2];
    int C = in_sizes[1] / N;
    float* out = (float*)d_out;

    k_zero<<<1, CLS_MAX>>>();
    k_normalize<<<N / 32, 256>>>(cls, tgt);
    k_ce<<<(N + 7) / 8, 256>>>(pred, tgt, N, C);

    cudaFuncSetAttribute(k_main, cudaFuncAttributeMaxDynamicSharedMemorySize, SMEM_MAIN);
    k_main<<<NJT * (NJT + 1) / 2, 256, SMEM_MAIN>>>(tgt);

    k_reduce<<<N / 8, 256>>>(tgt);
    k_final<<<1, 256>>>(tgt, out, N, C);
}

// round 4
// speedup vs baseline: 2.8019x; 1.0405x over previous
#include <cuda_runtime.h>
#include <math.h>

// SupConLoss fused, symmetric Gram pass with packed f32x2 FMAs (sm_103a).
// out = 0.5*ce + 0.5*cl + 0.25*triple   (ALPHA = 0.5)
// feats L2-normalized => Gram in [-1,1] => fixed softmax shifts exp((g-1)*10),
// exp((g-1)*20); partials are plain sums (mergeable, deterministic).
// Upper-triangular 128x128 tiles only; off-diagonal emits row AND col stats.

#define KD   128
#define NN   4096
#define CLS_MAX 64
#define NJT  32

typedef unsigned long long u64;

__device__ __forceinline__ void ffma2(u64 &d, u64 a, u64 b) {
    asm("fma.rn.f32x2 %0, %1, %2, %0;" : "+l"(d) : "l"(a), "l"(b));
}
__device__ __forceinline__ u64 splat2(float x) {
    u64 r; asm("mov.b64 %0, {%1, %1};" : "=l"(r) : "f"(x)); return r;
}
__device__ __forceinline__ void unpack2(u64 v, float &lo, float &hi) {
    asm("mov.b64 {%0, %1}, %2;" : "=f"(lo), "=f"(hi) : "l"(v));
}

__device__ __align__(16) float g_featsT[KD * NN];   // [k][row]
__device__ int    g_cnt[CLS_MAX];
__device__ float  g_rowCe[NN];
__device__ float  g_rowCl[NN];
__device__ float  g_rowR[NN];
__device__ float4 g_part[NN * NJT];                 // [row][slot]: sE, ssm, rs, maxg

// ---------------------------------------------------------------------------
__global__ void k_zero() {
    if (threadIdx.x < CLS_MAX) g_cnt[threadIdx.x] = 0;
}

__global__ void __launch_bounds__(256) k_normalize(const float* __restrict__ x,
                                                   const int* __restrict__ tgt) {
    __shared__ float s[32 * 129];
    int tid = threadIdx.x;
    int r = tid >> 3, l8 = tid & 7;
    int row = blockIdx.x * 32 + r;

    float v[16];
    const float4* xr = (const float4*)&x[row * KD + l8 * 16];
    float ss = 0.f;
    #pragma unroll
    for (int i = 0; i < 4; i++) {
        float4 q = xr[i];
        v[i * 4 + 0] = q.x; v[i * 4 + 1] = q.y; v[i * 4 + 2] = q.z; v[i * 4 + 3] = q.w;
        ss += q.x * q.x + q.y * q.y + q.z * q.z + q.w * q.w;
    }
    #pragma unroll
    for (int o = 4; o; o >>= 1) ss += __shfl_xor_sync(0xffffffffu, ss, o);
    float inv = 1.f / fmaxf(sqrtf(ss), 1e-12f);
    #pragma unroll
    for (int i = 0; i < 16; i++) s[r * 129 + l8 * 16 + i] = v[i] * inv;
    if (l8 == 0) atomicAdd(&g_cnt[tgt[row]], 1);
    __syncthreads();
    #pragma unroll
    for (int i = 0; i < 16; i++) {
        int idx = tid + i * 256;
        int rr = idx & 31, k = idx >> 5;
        g_featsT[k * NN + blockIdx.x * 32 + rr] = s[rr * 129 + k];
    }
}

__global__ void k_ce(const float* __restrict__ pred, const int* __restrict__ tgt,
                     int N, int C) {
    int row  = (int)((blockIdx.x * blockDim.x + threadIdx.x) >> 5);
    int lane = threadIdx.x & 31;
    if (row >= N) return;
    float v = (lane < C) ? pred[row * C + lane] : -1e30f;
    float mx = v;
    #pragma unroll
    for (int o = 16; o; o >>= 1) mx = fmaxf(mx, __shfl_xor_sync(0xffffffffu, mx, o));
    float e = (lane < C) ? __expf(v - mx) : 0.f;
    #pragma unroll
    for (int o = 16; o; o >>= 1) e += __shfl_xor_sync(0xffffffffu, e, o);
    int tg = tgt[row];
    float vt = __shfl_sync(0xffffffffu, v, tg);
    if (lane == 0) g_rowCe[row] = vt - mx - logf(e);
}

// ---------------------------------------------------------------------------
#define SMEM_MAIN (35840 + 1024)

__global__ void __launch_bounds__(256, 2) k_main(const int* __restrict__ tgt) {
    extern __shared__ float sm[];
    float*  s_a  = sm;                       // [32][128]
    float*  s_b  = sm + 32 * 128;            // [32][128]
    float4* part = (float4*)sm;              // [128][17] epilogue (overlaps tiles)
    int*    s_il = (int*)(sm + 35840 / 4);
    int*    s_jl = s_il + 128;

    int tid = threadIdx.x;
    int b = blockIdx.x, mt = 0;
    while (b >= NJT - mt) { b -= NJT - mt; mt++; }
    int jt = mt + b;
    int rowBase = mt * 128, jBase = jt * 128;

    if (tid < 128) s_il[tid] = tgt[rowBase + tid];
    else           s_jl[tid - 128] = tgt[jBase + (tid - 128)];

    int tr = tid & 15, tc = tid >> 4;

    // acc2[q][p2]: packed pair (p = 2*p2, 2*p2+1)
    u64 acc2[8][4];
    #pragma unroll
    for (int q = 0; q < 8; q++)
        #pragma unroll
        for (int p2 = 0; p2 < 4; p2++) acc2[q][p2] = 0ull;

    for (int kc = 0; kc < 4; kc++) {
        __syncthreads();
        #pragma unroll
        for (int i = 0; i < 4; i++) {
            int idx = tid + i * 256;
            int k = idx >> 5, c4 = idx & 31;
            *(float4*)&s_a[k * 128 + c4 * 4] =
                *(const float4*)&g_featsT[(kc * 32 + k) * NN + rowBase + c4 * 4];
            *(float4*)&s_b[k * 128 + c4 * 4] =
                *(const float4*)&g_featsT[(kc * 32 + k) * NN + jBase + c4 * 4];
        }
        __syncthreads();
        #pragma unroll 8
        for (int k = 0; k < 32; k++) {
            float4 a0 = *(const float4*)&s_a[k * 128 + tr * 4];
            float4 a1 = *(const float4*)&s_a[k * 128 + 64 + tr * 4];
            ulonglong2 B0 = *(const ulonglong2*)&s_b[k * 128 + tc * 4];
            ulonglong2 B1 = *(const ulonglong2*)&s_b[k * 128 + 64 + tc * 4];
            u64 am2[8];
            am2[0] = splat2(a0.x); am2[1] = splat2(a0.y);
            am2[2] = splat2(a0.z); am2[3] = splat2(a0.w);
            am2[4] = splat2(a1.x); am2[5] = splat2(a1.y);
            am2[6] = splat2(a1.z); am2[7] = splat2(a1.w);
            u64 bn2[4] = {B0.x, B0.y, B1.x, B1.y};
            #pragma unroll
            for (int q = 0; q < 8; q++)
                #pragma unroll
                for (int p2 = 0; p2 < 4; p2++)
                    ffma2(acc2[q][p2], am2[q], bn2[p2]);
        }
    }
    __syncthreads();   // tiles dead; smem reused

    // unpack accumulators
    float acc[8][8];
    #pragma unroll
    for (int q = 0; q < 8; q++)
        #pragma unroll
        for (int p2 = 0; p2 < 4; p2++)
            unpack2(acc2[q][p2], acc[q][2 * p2], acc[q][2 * p2 + 1]);

    int mr[8], nc[8];
    #pragma unroll
    for (int q = 0; q < 8; q++) mr[q] = tr * 4 + (q & 3) + ((q >> 2) << 6);
    #pragma unroll
    for (int p = 0; p < 8; p++) nc[p] = tc * 4 + (p & 3) + ((p >> 2) << 6);

    int ilab[8], jlab[8];
    #pragma unroll
    for (int q = 0; q < 8; q++) ilab[q] = s_il[mr[q]];
    #pragma unroll
    for (int p = 0; p < 8; p++) jlab[p] = s_jl[nc[p]];

    // ---- row stats ----
    {
        float sE[8], ssm[8], rs[8], bmx[8];
        #pragma unroll
        for (int q = 0; q < 8; q++) { sE[q] = 0.f; ssm[q] = 0.f; rs[q] = 0.f; bmx[q] = -2.f; }
        #pragma unroll
        for (int p = 0; p < 8; p++) {
            int jg = jBase + nc[p];
            #pragma unroll
            for (int q = 0; q < 8; q++) {
                float g = acc[q][p];
                float e10 = __expf(fmaf(g, 10.f, -10.f));
                if (jlab[p] == ilab[q]) {
                    if (jg != rowBase + mr[q]) { sE[q] += e10; ssm[q] += g; }
                } else {
                    rs[q] += e10 * e10;
                    bmx[q] = fmaxf(bmx[q], g);
                }
            }
        }
        #pragma unroll
        for (int q = 0; q < 8; q++)
            part[mr[q] * 17 + tc] = make_float4(sE[q], ssm[q], rs[q], bmx[q]);
        __syncthreads();
        if (tid < 128) {
            float a = 0.f, bb = 0.f, c = 0.f, d = -2.f;
            #pragma unroll
            for (int t = 0; t < 16; t++) {
                float4 v = part[tid * 17 + t];
                a += v.x; bb += v.y; c += v.z; d = fmaxf(d, v.w);
            }
            g_part[(rowBase + tid) * NJT + jt] = make_float4(a, bb, c, d);
        }
    }

    // ---- col stats (off-diagonal only) ----
    if (mt != jt) {
        __syncthreads();
        float sE[8], ssm[8], rs[8], bmx[8];
        #pragma unroll
        for (int p = 0; p < 8; p++) { sE[p] = 0.f; ssm[p] = 0.f; rs[p] = 0.f; bmx[p] = -2.f; }
        #pragma unroll
        for (int q = 0; q < 8; q++) {
            #pragma unroll
            for (int p = 0; p < 8; p++) {
                float g = acc[q][p];
                float e10 = __expf(fmaf(g, 10.f, -10.f));
                if (jlab[p] == ilab[q]) {
                    sE[p] += e10; ssm[p] += g;
                } else {
                    rs[p] += e10 * e10;
                    bmx[p] = fmaxf(bmx[p], g);
                }
            }
        }
        #pragma unroll
        for (int p = 0; p < 8; p++)
            part[nc[p] * 17 + tr] = make_float4(sE[p], ssm[p], rs[p], bmx[p]);
        __syncthreads();
        if (tid < 128) {
            float a = 0.f, bb = 0.f, c = 0.f, d = -2.f;
            #pragma unroll
            for (int t = 0; t < 16; t++) {
                float4 v = part[tid * 17 + t];
                a += v.x; bb += v.y; c += v.z; d = fmaxf(d, v.w);
            }
            g_part[(jBase + tid) * NJT + mt] = make_float4(a, bb, c, d);
        }
    }
}

// ---------------------------------------------------------------------------
__global__ void k_reduce(const int* __restrict__ tgt) {
    int row  = blockIdx.x * 8 + (threadIdx.x >> 5);
    int lane = threadIdx.x & 31;
    float4 v = g_part[row * NJT + lane];
    #pragma unroll
    for (int o = 16; o; o >>= 1) {
        v.x += __shfl_xor_sync(0xffffffffu, v.x, o);
        v.y += __shfl_xor_sync(0xffffffffu, v.y, o);
        v.z += __shfl_xor_sync(0xffffffffu, v.z, o);
        v.w = fmaxf(v.w, __shfl_xor_sync(0xffffffffu, v.w, o));
    }
    if (lane == 0) {
        int cnt = g_cnt[tgt[row]];
        int msum = cnt - 1;
        float clc = 0.f;
        if (msum > 0)
            clc = v.y * 10.f / (float)msum - 10.f - logf(v.x + 1e-12f);
        g_rowCl[row] = clc;
        float Bmax = fmaxf(0.f, v.w * 20.f);
        g_rowR[row] = v.z * expf(20.f - Bmax) + (float)cnt * expf(-Bmax);
    }
}

// ---------------------------------------------------------------------------
__global__ void k_final(const int* __restrict__ tgt, float* __restrict__ out,
                        int N, int C) {
    __shared__ float sred[256];
    __shared__ float classR[CLS_MAX];
    int t = threadIdx.x;
    int warp = t >> 5, lane = t & 31;

    float ce = 0.f, cl = 0.f;
    for (int i = t; i < N; i += 256) { ce += g_rowCe[i]; cl += g_rowCl[i]; }

    sred[t] = ce; __syncthreads();
    for (int s = 128; s; s >>= 1) { if (t < s) sred[t] += sred[t + s]; __syncthreads(); }
    float ceSum = sred[0]; __syncthreads();

    sred[t] = cl; __syncthreads();
    for (int s = 128; s; s >>= 1) { if (t < s) sred[t] += sred[t + s]; __syncthreads(); }
    float clSum = sred[0]; __syncthreads();

    for (int c = warp; c < C; c += 8) {
        float p = 0.f;
        for (int i = lane; i < N; i += 32) p += (tgt[i] == c) ? g_rowR[i] : 0.f;
        #pragma unroll
        for (int o = 16; o; o >>= 1) p += __shfl_xor_sync(0xffffffffu, p, o);
        if (lane == 0) classR[c] = p;
    }
    __syncthreads();

    if (t == 0) {
        float totalR = 0.f;
        long long total_c = 0;
        for (int c = 0; c < C; c++) {
            totalR += classR[c];
            long long cc = g_cnt[c];
            total_c += cc * (long long)(N - (int)cc);
        }
        bool all_zero = true;
        for (int c = 0; c < C; c++) {
            int cc = g_cnt[c];
            if (cc > 0) {
                long long ns = total_c - (long long)cc * (N - cc);
                if (ns != 0) { all_zero = false; break; }
            }
        }
        float tripleSum = 0.f;
        for (int c = 0; c < C; c++) {
            int cc = g_cnt[c];
            if (cc == 0) continue;
            float S = (N - cc > 0) ? (totalR - classR[c] + (float)cc * (float)N) : 0.f;
            long long ns = total_c - (long long)cc * (N - cc);
            float x = all_zero ? S : S / ((ns == 0) ? 1.0f : (float)ns);
            tripleSum += (float)cc * logf(x + 1e-12f);
        }
        float ce_loss = -ceSum / (float)N;
        float cl_loss = -clSum / (float)N;
        float triple  = tripleSum / (float)N;
        out[0] = 0.5f * ce_loss + 0.5f * cl_loss + 0.25f * triple;
    }
}

// ---------------------------------------------------------------------------
extern "C" void kernel_launch(void* const* d_in, const int* in_sizes, int n_in,
                              void* d_out, int out_size) {
    const float* cls  = (const float*)d_in[0];
    const float* pred = (const float*)d_in[1];
    const int*   tgt  = (const int*)d_in[2];
    int N = in_sizes[2];
    int C = in_sizes[1] / N;
    float* out = (float*)d_out;

    k_zero<<<1, CLS_MAX>>>();
    k_normalize<<<N / 32, 256>>>(cls, tgt);
    k_ce<<<(N + 7) / 8, 256>>>(pred, tgt, N, C);

    cudaFuncSetAttribute(k_main, cudaFuncAttributeMaxDynamicSharedMemorySize, SMEM_MAIN);
    k_main<<<NJT * (NJT + 1) / 2, 256, SMEM_MAIN>>>(tgt);

    k_reduce<<<N / 8, 256>>>(tgt);
    k_final<<<1, 256>>>(tgt, out, N, C);
}

// round 6
// speedup vs baseline: 3.4278x; 1.2234x over previous
#include <cuda_runtime.h>
#include <cuda_bf16.h>
#include <math.h>
#include <stdint.h>

// SupConLoss fused; Gram via bf16 mma.sync (hi/lo split, 3 matmuls). sm_103.
// out = 0.5*ce + 0.5*cl + 0.25*triple (ALPHA=0.5)
// feats L2-normalized => Gram in [-1,1] => fixed softmax shifts exp((g-1)*10),
// exp((g-1)*20); per-tile partials are plain sums (deterministic merge).
// Triangular tile grid; off-diagonal tiles emit row AND col stats.

#define KD   128
#define NN   4096
#define CLS_MAX 64
#define NJT  32

typedef unsigned long long u64;
typedef unsigned short u16;

__device__ __align__(16) __nv_bfloat16 g_hbf[NN * KD];
__device__ __align__(16) __nv_bfloat16 g_lbf[NN * KD];
__device__ int    g_cnt[CLS_MAX];
__device__ float  g_rowCe[NN];
__device__ float  g_rowCl[NN];
__device__ float  g_rowR[NN];
__device__ float4 g_part[NN * NJT];   // [row][slot]: sE, ssm, rs, maxg

// ---------------- PTX helpers ----------------
__device__ __forceinline__ uint32_t smem_u32(const void* p) {
    uint32_t a;
    asm("{ .reg .u64 t; cvta.to.shared.u64 t, %1; cvt.u32.u64 %0, t; }"
        : "=r"(a) : "l"(p));
    return a;
}
__device__ __forceinline__ void cp16(uint32_t s, const void* g) {
    asm volatile("cp.async.ca.shared.global [%0], [%1], 16;" :: "r"(s), "l"(g));
}
__device__ __forceinline__ void ldsm4(uint32_t* r, uint32_t addr) {
    asm volatile("ldmatrix.sync.aligned.m8n8.x4.shared.b16 {%0,%1,%2,%3}, [%4];"
        : "=r"(r[0]), "=r"(r[1]), "=r"(r[2]), "=r"(r[3]) : "r"(addr));
}
__device__ __forceinline__ void mma_bf16(float* d, const uint32_t* a, const uint32_t* b) {
    asm volatile("mma.sync.aligned.m16n8k16.row.col.f32.bf16.bf16.f32 "
        "{%0,%1,%2,%3}, {%4,%5,%6,%7}, {%8,%9}, {%0,%1,%2,%3};"
        : "+f"(d[0]), "+f"(d[1]), "+f"(d[2]), "+f"(d[3])
        : "r"(a[0]), "r"(a[1]), "r"(a[2]), "r"(a[3]), "r"(b[0]), "r"(b[1]));
}

// smem layout (dynamic): stage buffers 2 x (A 10240B + B 10240B) = 40960,
// then D tile float[128][136] = 69632. mrg overlays stage area.
#define STG_BYTES 20480
#define DT_OFF    40960
#define DT_STRIDE 136
#define SMEM_MAIN (40960 + 69632)

// ---------------------------------------------------------------------------
// CE (one warp per row, C<=32). Block 0 also zeroes g_cnt.
__global__ void k_ce(const float* __restrict__ pred, const int* __restrict__ tgt,
                     int N, int C) {
    if (blockIdx.x == 0 && threadIdx.x < CLS_MAX) g_cnt[threadIdx.x] = 0;
    int row  = (int)((blockIdx.x * blockDim.x + threadIdx.x) >> 5);
    int lane = threadIdx.x & 31;
    if (row >= N) return;
    float v = (lane < C) ? pred[row * C + lane] : -1e30f;
    float mx = v;
    #pragma unroll
    for (int o = 16; o; o >>= 1) mx = fmaxf(mx, __shfl_xor_sync(0xffffffffu, mx, o));
    float e = (lane < C) ? __expf(v - mx) : 0.f;
    #pragma unroll
    for (int o = 16; o; o >>= 1) e += __shfl_xor_sync(0xffffffffu, e, o);
    int tg = tgt[row];
    float vt = __shfl_sync(0xffffffffu, v, tg);
    if (lane == 0) g_rowCe[row] = vt - mx - logf(e);
}

// Normalize + bf16 hi/lo split (row-major) + class histogram. 32 rows/block.
__global__ void __launch_bounds__(256) k_prep(const float* __restrict__ x,
                                              const int* __restrict__ tgt) {
    int tid = threadIdx.x;
    int r = tid >> 3, l8 = tid & 7;
    int row = blockIdx.x * 32 + r;
    const float4* xr = (const float4*)&x[row * KD + l8 * 16];
    float4 q[4];
    float ss = 0.f;
    #pragma unroll
    for (int i = 0; i < 4; i++) {
        q[i] = xr[i];
        ss += q[i].x * q[i].x + q[i].y * q[i].y + q[i].z * q[i].z + q[i].w * q[i].w;
    }
    #pragma unroll
    for (int o = 4; o; o >>= 1) ss += __shfl_xor_sync(0xffffffffu, ss, o);
    float inv = 1.f / fmaxf(sqrtf(ss), 1e-12f);
    int base = row * KD + l8 * 16;
    u16 hs[16], ls[16];
    const float* qp = &q[0].x;
    #pragma unroll
    for (int c = 0; c < 16; c++) {
        float vv = qp[c] * inv;
        __nv_bfloat16 hb = __float2bfloat16(vv);
        float hf = __bfloat162float(hb);
        __nv_bfloat16 lb = __float2bfloat16(vv - hf);
        hs[c] = *(u16*)&hb;
        ls[c] = *(u16*)&lb;
    }
    *(uint4*)&g_hbf[base]     = *(uint4*)&hs[0];
    *(uint4*)&g_hbf[base + 8] = *(uint4*)&hs[8];
    *(uint4*)&g_lbf[base]     = *(uint4*)&ls[0];
    *(uint4*)&g_lbf[base + 8] = *(uint4*)&ls[8];
    if (l8 == 0) atomicAdd(&g_cnt[tgt[row]], 1);
}

// ---------------------------------------------------------------------------
// Main Gram pass: 528 triangular blocks (mt<=jt), 256 threads.
// K' = 384 (3 splits of K=128: Ahi*Bhi + Alo*Bhi + Ahi*Blo), 12 chunks of 32,
// cp.async double-buffered. Each warp: 32x64 region via m16n8k16 bf16 mma.
__global__ void __launch_bounds__(256, 2) k_main(const int* __restrict__ tgt) {
    extern __shared__ __align__(16) char smem[];
    __shared__ int s_il[128], s_jl[128];
    uint32_t smBase = smem_u32(smem);
    float* Dt = (float*)(smem + DT_OFF);
    float4* mrg = (float4*)smem;

    int tid = threadIdx.x, wid = tid >> 5, lane = tid & 31;
    int wr = wid & 3, wc = wid >> 2;

    int b = blockIdx.x, mt = 0;
    while (b >= NJT - mt) { b -= NJT - mt; mt++; }
    int jt = mt + b;
    int rowBase = mt * 128, jBase = jt * 128;

    if (tid < 128) s_il[tid] = tgt[rowBase + tid];
    else           s_jl[tid - 128] = tgt[jBase + (tid - 128)];

    // fill helper (inline): chunk c in 0..11
    int fr = tid >> 2, fseg = tid & 3;
    auto fill = [&](int stg, int c) {
        int s = c >> 2;
        const __nv_bfloat16* Ag = (s == 1) ? g_lbf : g_hbf;
        const __nv_bfloat16* Bg = (s == 2) ? g_lbf : g_hbf;
        int kcol = (c & 3) * 32;
        uint32_t sA = smBase + stg * STG_BYTES;
        uint32_t sB = sA + 10240;
        cp16(sA + fr * 80 + fseg * 16,        Ag + (rowBase + fr) * KD + kcol + fseg * 8);
        cp16(sA + (fr + 64) * 80 + fseg * 16, Ag + (rowBase + fr + 64) * KD + kcol + fseg * 8);
        cp16(sB + fr * 80 + fseg * 16,        Bg + (jBase + fr) * KD + kcol + fseg * 8);
        cp16(sB + (fr + 64) * 80 + fseg * 16, Bg + (jBase + fr + 64) * KD + kcol + fseg * 8);
        asm volatile("cp.async.commit_group;" ::: "memory");
    };

    float d[2][8][4];
    #pragma unroll
    for (int mi = 0; mi < 2; mi++)
        #pragma unroll
        for (int ni = 0; ni < 8; ni++)
            #pragma unroll
            for (int e = 0; e < 4; e++) d[mi][ni][e] = 0.f;

    fill(0, 0);
    fill(1, 1);

    int lr = lane & 7, s1 = (lane >> 3) & 1, s2 = lane >> 4;

    for (int c = 0; c < 12; c++) {
        if (c == 11) asm volatile("cp.async.wait_group 0;" ::: "memory");
        else         asm volatile("cp.async.wait_group 1;" ::: "memory");
        __syncthreads();
        uint32_t sA = smBase + (c & 1) * STG_BYTES;
        uint32_t sB = sA + 10240;
        #pragma unroll
        for (int kb = 0; kb < 32; kb += 16) {
            uint32_t a[2][4], bb[8][2];
            #pragma unroll
            for (int mi = 0; mi < 2; mi++)
                ldsm4(a[mi], sA + (uint32_t)((wr * 32 + mi * 16 + lr + s1 * 8) * 80
                                             + (kb + s2 * 8) * 2));
            #pragma unroll
            for (int pr = 0; pr < 4; pr++) {
                uint32_t t[4];
                ldsm4(t, sB + (uint32_t)((wc * 64 + pr * 16 + lr + s2 * 8) * 80
                                         + (kb + s1 * 8) * 2));
                bb[2 * pr][0] = t[0]; bb[2 * pr][1] = t[1];
                bb[2 * pr + 1][0] = t[2]; bb[2 * pr + 1][1] = t[3];
            }
            #pragma unroll
            for (int mi = 0; mi < 2; mi++)
                #pragma unroll
                for (int ni = 0; ni < 8; ni++)
                    mma_bf16(d[mi][ni], a[mi], bb[ni]);
        }
        __syncthreads();
        if (c + 2 < 12) fill(c & 1, c + 2);
    }

    // ---- dump D to smem tile [128][136] ----
    int dr = lane >> 2, dc = (lane & 3) * 2;
    #pragma unroll
    for (int mi = 0; mi < 2; mi++)
        #pragma unroll
        for (int ni = 0; ni < 8; ni++) {
            int row = wr * 32 + mi * 16 + dr;
            int col = wc * 64 + ni * 8 + dc;
            *(float2*)&Dt[row * DT_STRIDE + col] =
                make_float2(d[mi][ni][0], d[mi][ni][1]);
            *(float2*)&Dt[(row + 8) * DT_STRIDE + col] =
                make_float2(d[mi][ni][2], d[mi][ni][3]);
        }
    __syncthreads();

    // ---- row stats: thread (r = tid>>1, half h = tid&1) over 64 cols ----
    {
        int r = tid >> 1, h = tid & 1;
        int ilab = s_il[r];
        int rowg = rowBase + r;
        float sE = 0.f, ssm = 0.f, rs = 0.f, bmx = -2.f;
        const float* Dr = &Dt[r * DT_STRIDE + h * 64];
        #pragma unroll 8
        for (int cc = 0; cc < 64; cc++) {
            float g = Dr[cc];
            int cgl = h * 64 + cc;
            float e10 = __expf(fmaf(g, 10.f, -10.f));
            if (s_jl[cgl] == ilab) {
                if (jBase + cgl != rowg) { sE += e10; ssm += g; }
            } else {
                rs += e10 * e10;
                bmx = fmaxf(bmx, g);
            }
        }
        mrg[r * 2 + h] = make_float4(sE, ssm, rs, bmx);
        __syncthreads();
        if (tid < 128) {
            float4 x0 = mrg[tid * 2], x1 = mrg[tid * 2 + 1];
            g_part[(rowBase + tid) * NJT + jt] =
                make_float4(x0.x + x1.x, x0.y + x1.y, x0.z + x1.z, fmaxf(x0.w, x1.w));
        }
    }

    // ---- col stats (off-diagonal only) ----
    if (mt != jt) {
        __syncthreads();
        int cidx = tid >> 1, h = tid & 1;
        int jlab = s_jl[cidx];
        float sE = 0.f, ssm = 0.f, rs = 0.f, bmx = -2.f;
        #pragma unroll 8
        for (int rr = 0; rr < 64; rr++) {
            int rgl = h * 64 + rr;
            float g = Dt[rgl * DT_STRIDE + cidx];
            float e10 = __expf(fmaf(g, 10.f, -10.f));
            if (s_il[rgl] == jlab) {
                sE += e10; ssm += g;    // mt!=jt: never diagonal
            } else {
                rs += e10 * e10;
                bmx = fmaxf(bmx, g);
            }
        }
        mrg[cidx * 2 + h] = make_float4(sE, ssm, rs, bmx);
        __syncthreads();
        if (tid < 128) {
            float4 x0 = mrg[tid * 2], x1 = mrg[tid * 2 + 1];
            g_part[(jBase + tid) * NJT + mt] =
                make_float4(x0.x + x1.x, x0.y + x1.y, x0.z + x1.z, fmaxf(x0.w, x1.w));
        }
    }
}

// ---------------------------------------------------------------------------
__global__ void k_reduce(const int* __restrict__ tgt) {
    int row  = blockIdx.x * 8 + (threadIdx.x >> 5);
    int lane = threadIdx.x & 31;
    float4 v = g_part[row * NJT + lane];
    #pragma unroll
    for (int o = 16; o; o >>= 1) {
        v.x += __shfl_xor_sync(0xffffffffu, v.x, o);
        v.y += __shfl_xor_sync(0xffffffffu, v.y, o);
        v.z += __shfl_xor_sync(0xffffffffu, v.z, o);
        v.w = fmaxf(v.w, __shfl_xor_sync(0xffffffffu, v.w, o));
    }
    if (lane == 0) {
        int cnt = g_cnt[tgt[row]];
        int msum = cnt - 1;
        float clc = 0.f;
        if (msum > 0)
            clc = v.y * 10.f / (float)msum - 10.f - logf(v.x + 1e-12f);
        g_rowCl[row] = clc;
        float Bmax = fmaxf(0.f, v.w * 20.f);
        g_rowR[row] = v.z * expf(20.f - Bmax) + (float)cnt * expf(-Bmax);
    }
}

__global__ void k_final(const int* __restrict__ tgt, float* __restrict__ out,
                        int N, int C) {
    __shared__ float sred[256];
    __shared__ float classR[CLS_MAX];
    int t = threadIdx.x;
    int warp = t >> 5, lane = t & 31;

    float ce = 0.f, cl = 0.f;
    for (int i = t; i < N; i += 256) { ce += g_rowCe[i]; cl += g_rowCl[i]; }

    sred[t] = ce; __syncthreads();
    for (int s = 128; s; s >>= 1) { if (t < s) sred[t] += sred[t + s]; __syncthreads(); }
    float ceSum = sred[0]; __syncthreads();

    sred[t] = cl; __syncthreads();
    for (int s = 128; s; s >>= 1) { if (t < s) sred[t] += sred[t + s]; __syncthreads(); }
    float clSum = sred[0]; __syncthreads();

    for (int c = warp; c < C; c += 8) {
        float p = 0.f;
        for (int i = lane; i < N; i += 32) p += (tgt[i] == c) ? g_rowR[i] : 0.f;
        #pragma unroll
        for (int o = 16; o; o >>= 1) p += __shfl_xor_sync(0xffffffffu, p, o);
        if (lane == 0) classR[c] = p;
    }
    __syncthreads();

    if (t == 0) {
        float totalR = 0.f;
        long long total_c = 0;
        for (int c = 0; c < C; c++) {
            totalR += classR[c];
            long long cc = g_cnt[c];
            total_c += cc * (long long)(N - (int)cc);
        }
        bool all_zero = true;
        for (int c = 0; c < C; c++) {
            int cc = g_cnt[c];
            if (cc > 0) {
                long long ns = total_c - (long long)cc * (N - cc);
                if (ns != 0) { all_zero = false; break; }
            }
        }
        float tripleSum = 0.f;
        for (int c = 0; c < C; c++) {
            int cc = g_cnt[c];
            if (cc == 0) continue;
            float S = (N - cc > 0) ? (totalR - classR[c] + (float)cc * (float)N) : 0.f;
            long long ns = total_c - (long long)cc * (N - cc);
            float x = all_zero ? S : S / ((ns == 0) ? 1.0f : (float)ns);
            tripleSum += (float)cc * logf(x + 1e-12f);
        }
        float ce_loss = -ceSum / (float)N;
        float cl_loss = -clSum / (float)N;
        float triple  = tripleSum / (float)N;
        out[0] = 0.5f * ce_loss + 0.5f * cl_loss + 0.25f * triple;
    }
}

// ---------------------------------------------------------------------------
extern "C" void kernel_launch(void* const* d_in, const int* in_sizes, int n_in,
                              void* d_out, int out_size) {
    const float* cls  = (const float*)d_in[0];
    const float* pred = (const float*)d_in[1];
    const int*   tgt  = (const int*)d_in[2];
    int N = in_sizes[2];
    int C = in_sizes[1] / N;
    float* out = (float*)d_out;

    k_ce<<<(N + 7) / 8, 256>>>(pred, tgt, N, C);   // also zeroes g_cnt
    k_prep<<<N / 32, 256>>>(cls, tgt);

    cudaFuncSetAttribute(k_main, cudaFuncAttributeMaxDynamicSharedMemorySize, SMEM_MAIN);
    k_main<<<NJT * (NJT + 1) / 2, 256, SMEM_MAIN>>>(tgt);

    k_reduce<<<N / 8, 256>>>(tgt);
    k_final<<<1, 256>>>(tgt, out, N, C);
}

// round 7
// speedup vs baseline: 5.7049x; 1.6643x over previous
#include <cuda_runtime.h>
#include <cuda_bf16.h>
#include <math.h>
#include <stdint.h>

// SupConLoss fused; Gram via bf16 mma.sync (hi/lo split, 3 matmuls). sm_103.
// out = 0.5*ce + 0.5*cl + 0.25*triple (ALPHA=0.5)
// feats L2-normalized => Gram in [-1,1] => fixed softmax shifts exp((g-1)*10),
// exp((g-1)*20); per-tile partials are plain sums (deterministic merge).
// Triangular tile grid; off-diag tiles emit row AND col stats from registers.

#define KD   128
#define NN   4096
#define CLS_MAX 64
#define NJT  32

typedef unsigned long long u64;
typedef unsigned short u16;

__device__ __align__(16) __nv_bfloat16 g_hbf[NN * KD];
__device__ __align__(16) __nv_bfloat16 g_lbf[NN * KD];
__device__ int    g_cnt[CLS_MAX];           // zero-init; re-zeroed in k_final
__device__ float  g_rowCe[NN];
__device__ float4 g_part[NN * NJT];         // [row][slot]: sE, ssm, rs, maxg
__device__ float  g_blk[128 * 24];          // per-block partials: ce, cl, classR[22]

// ---------------- PTX helpers ----------------
__device__ __forceinline__ uint32_t smem_u32(const void* p) {
    uint32_t a;
    asm("{ .reg .u64 t; cvta.to.shared.u64 t, %1; cvt.u32.u64 %0, t; }"
        : "=r"(a) : "l"(p));
    return a;
}
__device__ __forceinline__ void cp16(uint32_t s, const void* g) {
    asm volatile("cp.async.ca.shared.global [%0], [%1], 16;" :: "r"(s), "l"(g));
}
__device__ __forceinline__ void ldsm4(uint32_t* r, uint32_t addr) {
    asm volatile("ldmatrix.sync.aligned.m8n8.x4.shared.b16 {%0,%1,%2,%3}, [%4];"
        : "=r"(r[0]), "=r"(r[1]), "=r"(r[2]), "=r"(r[3]) : "r"(addr));
}
__device__ __forceinline__ void mma_bf16(float* d, const uint32_t* a, const uint32_t* b) {
    asm volatile("mma.sync.aligned.m16n8k16.row.col.f32.bf16.bf16.f32 "
        "{%0,%1,%2,%3}, {%4,%5,%6,%7}, {%8,%9}, {%0,%1,%2,%3};"
        : "+f"(d[0]), "+f"(d[1]), "+f"(d[2]), "+f"(d[3])
        : "r"(a[0]), "r"(a[1]), "r"(a[2]), "r"(a[3]), "r"(b[0]), "r"(b[1]));
}

// smem: 3 stage buffers (A 10240 + B 10240 each) then colPart/rowPart
#define STG_BYTES 20480
#define CP_OFF    61440
#define RP_OFF    69632
#define SMEM_MAIN 73728

// ---------------------------------------------------------------------------
// Fused prep (normalize + bf16 hi/lo split + histogram) and CE.
__global__ void __launch_bounds__(256) k_pre(const float* __restrict__ x,
                                             const float* __restrict__ pred,
                                             const int* __restrict__ tgt,
                                             int N, int C) {
    int tid = threadIdx.x;
    if (blockIdx.x < (unsigned)(N / 32)) {
        // ---- prep: 32 rows/block ----
        int r = tid >> 3, l8 = tid & 7;
        int row = blockIdx.x * 32 + r;
        const float4* xr = (const float4*)&x[row * KD + l8 * 16];
        float4 q[4];
        float ss = 0.f;
        #pragma unroll
        for (int i = 0; i < 4; i++) {
            q[i] = xr[i];
            ss += q[i].x * q[i].x + q[i].y * q[i].y + q[i].z * q[i].z + q[i].w * q[i].w;
        }
        #pragma unroll
        for (int o = 4; o; o >>= 1) ss += __shfl_xor_sync(0xffffffffu, ss, o);
        float inv = 1.f / fmaxf(sqrtf(ss), 1e-12f);
        int base = row * KD + l8 * 16;
        u16 hs[16], ls[16];
        const float* qp = &q[0].x;
        #pragma unroll
        for (int c = 0; c < 16; c++) {
            float vv = qp[c] * inv;
            __nv_bfloat16 hb = __float2bfloat16(vv);
            float hf = __bfloat162float(hb);
            __nv_bfloat16 lb = __float2bfloat16(vv - hf);
            hs[c] = *(u16*)&hb;
            ls[c] = *(u16*)&lb;
        }
        *(uint4*)&g_hbf[base]     = *(uint4*)&hs[0];
        *(uint4*)&g_hbf[base + 8] = *(uint4*)&hs[8];
        *(uint4*)&g_lbf[base]     = *(uint4*)&ls[0];
        *(uint4*)&g_lbf[base + 8] = *(uint4*)&ls[8];
        if (l8 == 0) atomicAdd(&g_cnt[tgt[row]], 1);
    } else {
        // ---- CE: one warp per row (C<=32) ----
        int bid = blockIdx.x - N / 32;
        int row  = bid * 8 + (tid >> 5);
        int lane = tid & 31;
        if (row >= N) return;
        float v = (lane < C) ? pred[row * C + lane] : -1e30f;
        float mx = v;
        #pragma unroll
        for (int o = 16; o; o >>= 1) mx = fmaxf(mx, __shfl_xor_sync(0xffffffffu, mx, o));
        float e = (lane < C) ? __expf(v - mx) : 0.f;
        #pragma unroll
        for (int o = 16; o; o >>= 1) e += __shfl_xor_sync(0xffffffffu, e, o);
        int tg = tgt[row];
        float vt = __shfl_sync(0xffffffffu, v, tg);
        if (lane == 0) g_rowCe[row] = vt - mx - logf(e);
    }
}

// ---------------------------------------------------------------------------
// Main Gram pass: 528 triangular blocks (mt<=jt), 256 threads.
// K' = 384 (Ahi*Bhi + Alo*Bhi + Ahi*Blo), 12 chunks of 32, 3-stage cp.async.
// Epilogue fused in registers: one exp per element feeds row AND col stats.
__global__ void __launch_bounds__(256, 2) k_main(const int* __restrict__ tgt) {
    extern __shared__ __align__(16) char smem[];
    __shared__ int s_il[128], s_jl[128];
    uint32_t smBase = smem_u32(smem);
    float4* colPart = (float4*)(smem + CP_OFF);   // [128 cols][4 wr]
    float4* rowPart = (float4*)(smem + RP_OFF);   // [128 rows][2 wc]

    int tid = threadIdx.x, wid = tid >> 5, lane = tid & 31;
    int wr = wid & 3, wc = wid >> 2;

    int b = blockIdx.x, mt = 0;
    while (b >= NJT - mt) { b -= NJT - mt; mt++; }
    int jt = mt + b;
    int rowBase = mt * 128, jBase = jt * 128;
    bool isDiag = (mt == jt);

    if (tid < 128) s_il[tid] = tgt[rowBase + tid];
    else           s_jl[tid - 128] = tgt[jBase + (tid - 128)];

    int fr = tid >> 2, fseg = tid & 3;
    auto fill = [&](int stg, int c) {
        int s = c >> 2;
        const __nv_bfloat16* Ag = (s == 1) ? g_lbf : g_hbf;
        const __nv_bfloat16* Bg = (s == 2) ? g_lbf : g_hbf;
        int kcol = (c & 3) * 32;
        uint32_t sA = smBase + stg * STG_BYTES;
        uint32_t sB = sA + 10240;
        cp16(sA + fr * 80 + fseg * 16,        Ag + (rowBase + fr) * KD + kcol + fseg * 8);
        cp16(sA + (fr + 64) * 80 + fseg * 16, Ag + (rowBase + fr + 64) * KD + kcol + fseg * 8);
        cp16(sB + fr * 80 + fseg * 16,        Bg + (jBase + fr) * KD + kcol + fseg * 8);
        cp16(sB + (fr + 64) * 80 + fseg * 16, Bg + (jBase + fr + 64) * KD + kcol + fseg * 8);
        asm volatile("cp.async.commit_group;" ::: "memory");
    };

    float d[2][8][4];
    #pragma unroll
    for (int mi = 0; mi < 2; mi++)
        #pragma unroll
        for (int ni = 0; ni < 8; ni++)
            #pragma unroll
            for (int e = 0; e < 4; e++) d[mi][ni][e] = 0.f;

    fill(0, 0); fill(1, 1); fill(2, 2);

    int lr = lane & 7, s1 = (lane >> 3) & 1, s2 = lane >> 4;

    for (int c = 0; c < 12; c++) {
        if (c < 10)      asm volatile("cp.async.wait_group 2;" ::: "memory");
        else if (c == 10) asm volatile("cp.async.wait_group 1;" ::: "memory");
        else              asm volatile("cp.async.wait_group 0;" ::: "memory");
        __syncthreads();
        int stg = c % 3;
        uint32_t sA = smBase + stg * STG_BYTES;
        uint32_t sB = sA + 10240;
        #pragma unroll
        for (int kb = 0; kb < 32; kb += 16) {
            uint32_t a[2][4], bb[8][2];
            #pragma unroll
            for (int mi = 0; mi < 2; mi++)
                ldsm4(a[mi], sA + (uint32_t)((wr * 32 + mi * 16 + lr + s1 * 8) * 80
                                             + (kb + s2 * 8) * 2));
            #pragma unroll
            for (int pr = 0; pr < 4; pr++) {
                uint32_t t[4];
                ldsm4(t, sB + (uint32_t)((wc * 64 + pr * 16 + lr + s2 * 8) * 80
                                         + (kb + s1 * 8) * 2));
                bb[2 * pr][0] = t[0]; bb[2 * pr][1] = t[1];
                bb[2 * pr + 1][0] = t[2]; bb[2 * pr + 1][1] = t[3];
            }
            #pragma unroll
            for (int mi = 0; mi < 2; mi++)
                #pragma unroll
                for (int ni = 0; ni < 8; ni++)
                    mma_bf16(d[mi][ni], a[mi], bb[ni]);
        }
        __syncthreads();
        if (c + 3 < 12) fill(stg, c + 3);
    }

    // ---- fused register epilogue ----
    int lr4 = lane >> 2, lc2 = lane & 3;
    int il[4];
    #pragma unroll
    for (int s = 0; s < 4; s++) il[s] = s_il[wr * 32 + s * 8 + lr4];

    float rE[4], rS[4], rR[4], rB[4];
    #pragma unroll
    for (int s = 0; s < 4; s++) { rE[s] = 0.f; rS[s] = 0.f; rR[s] = 0.f; rB[s] = -2.f; }

    #pragma unroll
    for (int ni = 0; ni < 8; ni++) {
        int c0 = wc * 64 + ni * 8 + lc2 * 2;
        int jl0 = s_jl[c0], jl1 = s_jl[c0 + 1];
        float cE0 = 0.f, cS0 = 0.f, cR0 = 0.f, cB0 = -2.f;
        float cE1 = 0.f, cS1 = 0.f, cR1 = 0.f, cB1 = -2.f;
        #pragma unroll
        for (int mi = 0; mi < 2; mi++) {
            #pragma unroll
            for (int e = 0; e < 4; e++) {
                int sub = mi * 2 + (e >> 1);
                float g = d[mi][ni][e];
                float e10 = __expf(fmaf(g, 10.f, -10.f));
                int jl = (e & 1) ? jl1 : jl0;
                bool same = (jl == il[sub]);
                bool diag = isDiag && ((c0 + (e & 1)) == (wr * 32 + sub * 8 + lr4));
                if (same) {
                    if (!diag) {
                        rE[sub] += e10; rS[sub] += g;
                        if (e & 1) { cE1 += e10; cS1 += g; }
                        else       { cE0 += e10; cS0 += g; }
                    }
                } else {
                    float e20 = e10 * e10;
                    rR[sub] += e20; rB[sub] = fmaxf(rB[sub], g);
                    if (e & 1) { cR1 += e20; cB1 = fmaxf(cB1, g); }
                    else       { cR0 += e20; cB0 = fmaxf(cB0, g); }
                }
            }
        }
        #pragma unroll
        for (int o = 4; o <= 16; o <<= 1) {
            cE0 += __shfl_xor_sync(0xffffffffu, cE0, o);
            cS0 += __shfl_xor_sync(0xffffffffu, cS0, o);
            cR0 += __shfl_xor_sync(0xffffffffu, cR0, o);
            cB0 = fmaxf(cB0, __shfl_xor_sync(0xffffffffu, cB0, o));
            cE1 += __shfl_xor_sync(0xffffffffu, cE1, o);
            cS1 += __shfl_xor_sync(0xffffffffu, cS1, o);
            cR1 += __shfl_xor_sync(0xffffffffu, cR1, o);
            cB1 = fmaxf(cB1, __shfl_xor_sync(0xffffffffu, cB1, o));
        }
        if (lr4 == 0) {
            colPart[c0 * 4 + wr]       = make_float4(cE0, cS0, cR0, cB0);
            colPart[(c0 + 1) * 4 + wr] = make_float4(cE1, cS1, cR1, cB1);
        }
    }
    #pragma unroll
    for (int s = 0; s < 4; s++) {
        #pragma unroll
        for (int o = 1; o <= 2; o <<= 1) {
            rE[s] += __shfl_xor_sync(0xffffffffu, rE[s], o);
            rS[s] += __shfl_xor_sync(0xffffffffu, rS[s], o);
            rR[s] += __shfl_xor_sync(0xffffffffu, rR[s], o);
            rB[s] = fmaxf(rB[s], __shfl_xor_sync(0xffffffffu, rB[s], o));
        }
    }
    if (lc2 == 0) {
        #pragma unroll
        for (int s = 0; s < 4; s++)
            rowPart[(wr * 32 + s * 8 + lr4) * 2 + wc] = make_float4(rE[s], rS[s], rR[s], rB[s]);
    }
    __syncthreads();
    if (tid < 128) {
        float4 a = rowPart[tid * 2], b2 = rowPart[tid * 2 + 1];
        g_part[(rowBase + tid) * NJT + jt] =
            make_float4(a.x + b2.x, a.y + b2.y, a.z + b2.z, fmaxf(a.w, b2.w));
    } else if (!isDiag) {
        int cc = tid - 128;
        float4 x0 = colPart[cc * 4 + 0], x1 = colPart[cc * 4 + 1];
        float4 x2 = colPart[cc * 4 + 2], x3 = colPart[cc * 4 + 3];
        g_part[(jBase + cc) * NJT + mt] = make_float4(
            x0.x + x1.x + x2.x + x3.x,
            x0.y + x1.y + x2.y + x3.y,
            x0.z + x1.z + x2.z + x3.z,
            fmaxf(fmaxf(x0.w, x1.w), fmaxf(x2.w, x3.w)));
    }
}

// ---------------------------------------------------------------------------
// 128 blocks; block b handles rows b*32..b*32+31: merges 32 tile partials per
// row, then emits per-block partials: {ceSum, clSum, classR[0..C-1]}.
__global__ void k_reduce(const int* __restrict__ tgt, int C) {
    __shared__ float rcl[32], rRb[32], rce[32];
    __shared__ int   labb[32];
    int tid = threadIdx.x, warp = tid >> 5, lane = tid & 31;
    int bb = blockIdx.x;

    if (tid < 32) rce[tid] = g_rowCe[bb * 32 + tid];

    #pragma unroll
    for (int it = 0; it < 4; it++) {
        int r = bb * 32 + it * 8 + warp;
        float4 v = g_part[r * NJT + lane];
        #pragma unroll
        for (int o = 16; o; o >>= 1) {
            v.x += __shfl_xor_sync(0xffffffffu, v.x, o);
            v.y += __shfl_xor_sync(0xffffffffu, v.y, o);
            v.z += __shfl_xor_sync(0xffffffffu, v.z, o);
            v.w = fmaxf(v.w, __shfl_xor_sync(0xffffffffu, v.w, o));
        }
        if (lane == 0) {
            int lb = tgt[r];
            int cnt = g_cnt[lb];
            int msum = cnt - 1;
            float clc = 0.f;
            if (msum > 0)
                clc = v.y * 10.f / (float)msum - 10.f - logf(v.x + 1e-12f);
            float Bmax = fmaxf(0.f, v.w * 20.f);
            rcl[it * 8 + warp] = clc;
            rRb[it * 8 + warp] = v.z * expf(20.f - Bmax) + (float)cnt * expf(-Bmax);
            labb[it * 8 + warp] = lb;
        }
    }
    __syncthreads();
    if (warp == 0) {
        float s = rcl[lane];
        #pragma unroll
        for (int o = 16; o; o >>= 1) s += __shfl_xor_sync(0xffffffffu, s, o);
        if (lane == 0) g_blk[bb * 24 + 1] = s;
    } else if (warp == 1) {
        float s = rce[lane];
        #pragma unroll
        for (int o = 16; o; o >>= 1) s += __shfl_xor_sync(0xffffffffu, s, o);
        if (lane == 0) g_blk[bb * 24 + 0] = s;
    }
    if (tid >= 64 && tid < 64 + C) {
        int c = tid - 64;
        float s = 0.f;
        #pragma unroll
        for (int i = 0; i < 32; i++) s += (labb[i] == c) ? rRb[i] : 0.f;
        g_blk[bb * 24 + 2 + c] = s;
    }
}

// ---------------------------------------------------------------------------
__global__ void k_final(float* __restrict__ out, int N, int C) {
    __shared__ float fld[24];
    int t = threadIdx.x, warp = t >> 5, lane = t & 31;
    for (int f = warp; f < 2 + C; f += 8) {
        float s = 0.f;
        #pragma unroll
        for (int k = 0; k < 4; k++) s += g_blk[(lane + k * 32) * 24 + f];
        #pragma unroll
        for (int o = 16; o; o >>= 1) s += __shfl_xor_sync(0xffffffffu, s, o);
        if (lane == 0) fld[f] = s;
    }
    __syncthreads();
    if (t == 0) {
        float ceSum = fld[0], clSum = fld[1];
        float totalR = 0.f;
        long long total_c = 0;
        for (int c = 0; c < C; c++) {
            totalR += fld[2 + c];
            long long cc = g_cnt[c];
            total_c += cc * (long long)(N - (int)cc);
        }
        bool all_zero = true;
        for (int c = 0; c < C; c++) {
            int cc = g_cnt[c];
            if (cc > 0) {
                long long ns = total_c - (long long)cc * (N - cc);
                if (ns != 0) { all_zero = false; break; }
            }
        }
        float tripleSum = 0.f;
        for (int c = 0; c < C; c++) {
            int cc = g_cnt[c];
            if (cc == 0) continue;
            float S = (N - cc > 0) ? (totalR - fld[2 + c] + (float)cc * (float)N) : 0.f;
            long long ns = total_c - (long long)cc * (N - cc);
            float x = all_zero ? S : S / ((ns == 0) ? 1.0f : (float)ns);
            tripleSum += (float)cc * logf(x + 1e-12f);
        }
        float ce_loss = -ceSum / (float)N;
        float cl_loss = -clSum / (float)N;
        float triple  = tripleSum / (float)N;
        out[0] = 0.5f * ce_loss + 0.5f * cl_loss + 0.25f * triple;
    }
    __syncthreads();
    if (t < CLS_MAX) g_cnt[t] = 0;   // leave zeroed for the next invocation
}

// ---------------------------------------------------------------------------
extern "C" void kernel_launch(void* const* d_in, const int* in_sizes, int n_in,
                              void* d_out, int out_size) {
    const float* cls  = (const float*)d_in[0];
    const float* pred = (const float*)d_in[1];
    const int*   tgt  = (const int*)d_in[2];
    int N = in_sizes[2];
    int C = in_sizes[1] / N;
    float* out = (float*)d_out;

    k_pre<<<N / 32 + N / 8, 256>>>(cls, pred, tgt, N, C);

    cudaFuncSetAttribute(k_main, cudaFuncAttributeMaxDynamicSharedMemorySize, SMEM_MAIN);
    k_main<<<NJT * (NJT + 1) / 2, 256, SMEM_MAIN>>>(tgt);

    k_reduce<<<N / 32, 256>>>(tgt, C);
    k_final<<<1, 256>>>(out, N, C);
}